// round 14
// baseline (speedup 1.0000x reference)
#include <cuda_runtime.h>
#include <cuda_bf16.h>
#include <cstdint>
#include <math.h>

#define BSZ   4096
#define NSTEP 30
#define PROBS_STRIDE (31*256)
#define PROBS_TOTAL  (4096*31*256)

// ======================= device images (no allocs allowed) =======================
__device__ __align__(128) __nv_bfloat16 g_prob[3][32][4][8192];
__device__ __align__(128) __nv_bfloat16 g_tags[3][32][2][8192];
__device__ __align__(128) __nv_bfloat16 g_hs[2][3][3][32][4][8192];
__device__ __align__(128) __nv_bfloat16 g_w0[3][4][10][16384];
__device__ __align__(128) __nv_bfloat16 g_w12[2][3][4][8][16384];
__device__ __align__(128) __nv_bfloat16 g_wlin[3][4][16384];
__device__ float g_bias[3][2][1024];
__device__ float g_cst[3][BSZ*256];

// ======================= helpers =======================
__device__ __forceinline__ float sigf(float x) { return 1.0f / (1.0f + expf(-x)); }

__device__ __forceinline__ void split3(float x, __nv_bfloat16& a, __nv_bfloat16& b, __nv_bfloat16& c) {
    a = __float2bfloat16_rn(x);
    float r = x - __bfloat162float(a);
    b = __float2bfloat16_rn(r);
    float r2 = r - __bfloat162float(b);
    c = __float2bfloat16_rn(r2);
}

__device__ __forceinline__ uint32_t smem_u32(const void* p) {
    uint32_t a;
    asm("{ .reg .u64 t; cvta.to.shared.u64 t, %1; cvt.u32.u64 %0, t; }" : "=r"(a) : "l"(p));
    return a;
}

__device__ __forceinline__ void ldsm4(uint32_t* r, uint32_t addr) {
    asm volatile("ldmatrix.sync.aligned.m8n8.x4.shared.b16 {%0,%1,%2,%3}, [%4];"
                 : "=r"(r[0]), "=r"(r[1]), "=r"(r[2]), "=r"(r[3]) : "r"(addr));
}

__device__ __forceinline__ void mma16816(float* c, const uint32_t* a, uint32_t b0, uint32_t b1) {
    asm volatile(
        "mma.sync.aligned.m16n8k16.row.col.f32.bf16.bf16.f32 "
        "{%0,%1,%2,%3}, {%4,%5,%6,%7}, {%8,%9}, {%0,%1,%2,%3};"
        : "+f"(c[0]), "+f"(c[1]), "+f"(c[2]), "+f"(c[3])
        : "r"(a[0]), "r"(a[1]), "r"(a[2]), "r"(a[3]), "r"(b0), "r"(b1));
}

__device__ __forceinline__ void cpa16(uint32_t s, const char* g) {
    asm volatile("cp.async.cg.shared.global [%0], [%1], 16;" :: "r"(s), "l"(g));
}

// ======================= prologue kernels (2 launches) ==========
__global__ void k_setup(const float* __restrict__ tags,
                        const float* __restrict__ bih0, const float* __restrict__ bhh0,
                        const float* __restrict__ bih,  const float* __restrict__ bhh,
                        float* __restrict__ d_out) {
    long i = (long)blockIdx.x * blockDim.x + threadIdx.x;
    const long N1 = 3L * BSZ * 256;
    const long N2 = 3L * 3 * 32 * 4 * 8192 / 2;
    const long N3 = (long)BSZ * 256;
    const long N4 = (long)BSZ * 128;
    const long N5 = 3 * 1024;
    if (i < N1) { ((float*)g_cst)[i] = 0.f; return; }
    i -= N1;
    if (i < N2) { ((uint32_t*)g_hs[0])[i] = 0u; return; }
    i -= N2;
    if (i < N3) {
        int b = (int)(i >> 8), a = (int)(i & 255);
        float v = (a == 1) ? 1.0f : 0.0f;
        d_out[b * PROBS_STRIDE + a] = v;
        int rb = b >> 7, row = b & 127, ch = a >> 6, col = a & 63;
        int off = row * 64 + col;
        g_prob[0][rb][ch][off] = __float2bfloat16_rn(v);
        g_prob[1][rb][ch][off] = __float2bfloat16_rn(0.f);
        g_prob[2][rb][ch][off] = __float2bfloat16_rn(0.f);
        return;
    }
    i -= N3;
    if (i < N4) {
        int b = (int)(i >> 7), k = (int)(i & 127);
        __nv_bfloat16 s1, s2, s3;
        split3(tags[b * 128 + k], s1, s2, s3);
        int rb = b >> 7, row = b & 127, ch = k >> 6, col = k & 63;
        int off = row * 64 + col;
        g_tags[0][rb][ch][off] = s1;
        g_tags[1][rb][ch][off] = s2;
        g_tags[2][rb][ch][off] = s3;
        return;
    }
    i -= N4;
    if (i < N5) {
        int l = (int)(i >> 10), n = (int)(i & 1023);
        int u = n >> 2, g = n & 3;
        int src = g * 256 + u;
        if (l == 0) {
            g_bias[0][0][n] = bih0[src];
            g_bias[0][1][n] = bhh0[src];
        } else {
            g_bias[l][0][n] = bih[(l - 1) * 1024 + src];
            g_bias[l][1][n] = bhh[(l - 1) * 1024 + src];
        }
    }
}

__global__ void k_build_w(const float* __restrict__ Wih0, const float* __restrict__ Whh0,
                          const float* __restrict__ Wih,  const float* __restrict__ Whh,
                          const float* __restrict__ linW) {
    int i = blockIdx.x * blockDim.x + threadIdx.x;
    if (i < 1024 * 640) {
        int n = i / 640, k = i % 640;
        int u = n >> 2, g = n & 3;
        int src = g * 256 + u;
        float v = (k < 384) ? Wih0[src * 384 + k] : Whh0[src * 256 + (k - 384)];
        __nv_bfloat16 s1, s2, s3;
        split3(v, s1, s2, s3);
        int nb = n >> 8, row = n & 255, ch = k >> 6, col = k & 63;
        int off = row * 64 + col;
        g_w0[0][nb][ch][off] = s1;
        g_w0[1][nb][ch][off] = s2;
        g_w0[2][nb][ch][off] = s3;
        return;
    }
    i -= 1024 * 640;
    if (i < 2 * 1024 * 512) {
        int l = i / (1024 * 512);
        int r = i % (1024 * 512);
        int n = r / 512, k = r % 512;
        int u = n >> 2, g = n & 3;
        int src = g * 256 + u;
        float v = (k < 256) ? Wih[(l * 1024 + src) * 256 + k] : Whh[(l * 1024 + src) * 256 + (k - 256)];
        __nv_bfloat16 s1, s2, s3;
        split3(v, s1, s2, s3);
        int nb = n >> 8, row = n & 255, ch = k >> 6, col = k & 63;
        int off = row * 64 + col;
        g_w12[l][0][nb][ch][off] = s1;
        g_w12[l][1][nb][ch][off] = s2;
        g_w12[l][2][nb][ch][off] = s3;
        return;
    }
    i -= 2 * 1024 * 512;
    if (i < 256 * 256) {
        int n = i >> 8, k = i & 255;
        __nv_bfloat16 s1, s2, s3;
        split3(linW[n * 256 + k], s1, s2, s3);
        int ch = k >> 6, col = k & 63;
        int off = n * 64 + col;
        g_wlin[0][ch][off] = s1;
        g_wlin[1][ch][off] = s2;
        g_wlin[2][ch][off] = s3;
    }
}

// ======================= fused mma.sync GEMM — chunk-outer, all-splits staged =======================
// CTA tile 128 rows x 128 gate-cols; 512 threads; 16 warps 4(m) x 4(n); warp tile 32x32.
// Per k-chunk: stage A0,A1,A2,B0,B1,B2 once; compute corrections (small mags first)
// then main; bank acc->run per chunk (error structure = R8's; realization differs).
#define TILE_B  18432                  // 128 rows x 144B
#define STAGE_B (6*TILE_B)             // 110592
#define SMEM_TOTAL (2*STAGE_B + 512)   // 221696

template<int MODE>
__device__ __forceinline__ const char* a_chunk(int ai, int c, int rb, int layer, int par) {
    if (MODE == 0) {
        if (c < 4) return (const char*)&g_prob[ai][rb][c][0];
        if (c < 6) return (const char*)&g_tags[ai][rb][c - 4][0];
        return (const char*)&g_hs[par][0][ai][rb][c - 6][0];
    } else if (MODE == 1) {
        if (c < 4) return (const char*)&g_hs[par ^ 1][layer - 1][ai][rb][c][0];
        return (const char*)&g_hs[par][layer][ai][rb][c - 4][0];
    } else {
        return (const char*)&g_hs[par ^ 1][2][ai][rb][c][0];
    }
}

// 128-gate (nb) sub-block of a [256 x 64] weight chunk: (nb&1)*1024 uint4
template<int MODE>
__device__ __forceinline__ const char* b_chunk(int bi, int c, int nb, int layer) {
    if (MODE == 0)      return (const char*)((const uint4*)&g_w0[bi][nb >> 1][c][0] + (nb & 1) * 1024);
    else if (MODE == 1) return (const char*)((const uint4*)&g_w12[layer - 1][bi][nb >> 1][c][0] + (nb & 1) * 1024);
    else                return (const char*)((const uint4*)&g_wlin[bi][c][0] + nb * 1024);
}

template<int MODE>
__global__ __launch_bounds__(512, 1) void mma_kernel(
    int layer, int par, int step, const float* __restrict__ lin_b, float* __restrict__ d_out)
{
    extern __shared__ __align__(16) char smem[];
    const int KC  = (MODE == 0) ? 10 : (MODE == 1 ? 8 : 4);
    const int rb = blockIdx.x, nb = blockIdx.y;
    const int tid = threadIdx.x;
    const int wid = tid >> 5, lane = tid & 31;
    const int wm = wid >> 2, wn = wid & 3;      // 4 (m) x 4 (n); warp tile 32 rows x 32 gates
    uint32_t sb = smem_u32(smem);

    const char** tab = (const char**)(smem + 2 * STAGE_B);   // [KC][6]: A0,A1,A2,B0,B1,B2

    if (tid < KC * 6) {
        int c = tid / 6, t = tid - c * 6;
        tab[tid] = (t < 3) ? a_chunk<MODE>(t, c, rb, layer, par)
                           : b_chunk<MODE>(t - 3, c, nb, layer);
    }

    // per-thread staging offsets: 2 uint4 per tile (1024 uint4 / 512 threads)
    uint32_t goff[2], soff[2];
#pragma unroll
    for (int i = 0; i < 2; i++) {
        int idx = tid + (i << 9);
        goff[i] = (uint32_t)idx * 16u;
        soff[i] = (idx >> 3) * 144 + (idx & 7) * 16;
    }

    float acc[2][4][4];
    float run[2][4][4];
#pragma unroll
    for (int a = 0; a < 2; a++)
#pragma unroll
        for (int b = 0; b < 4; b++)
#pragma unroll
            for (int c = 0; c < 4; c++) { acc[a][b][c] = 0.f; run[a][b][c] = 0.f; }

    __syncthreads();   // table visible

    auto issue = [&](int ch, int stg) {
        uint32_t S = sb + stg * STAGE_B;
#pragma unroll
        for (int t = 0; t < 6; t++) {
            const char* g = tab[ch * 6 + t];
            uint32_t s = S + t * TILE_B;
            cpa16(s + soff[0], g + goff[0]);
            cpa16(s + soff[1], g + goff[1]);
        }
        asm volatile("cp.async.commit_group;" ::: "memory");
    };

    issue(0, 0);

    const uint32_t lane_off = (lane & 15) * 144 + (lane >> 4) * 16;

    int stg = 0;
    for (int ch = 0; ch < KC; ch++) {
        asm volatile("cp.async.wait_group 0;" ::: "memory");
        __syncthreads();                       // prev compute on stg^1 done; chunk ch resident
        if (ch + 1 < KC) issue(ch + 1, stg ^ 1);

        uint32_t S  = sb + stg * STAGE_B;
        uint32_t aW = S + wm * (32 * 144) + lane_off;
        uint32_t bW = S + 3 * TILE_B + wn * (32 * 144) + lane_off;

        // ---- phase 1: correction passes (2,0),(1,0),(1,1),(0,1),(0,2) ----
#pragma unroll
        for (int k16 = 0; k16 < 4; k16++) {
            uint32_t kk = (uint32_t)k16 * 32;
            uint32_t afr[2][4], bfr[2][4];
            ldsm4(bfr[0], bW + 0 * TILE_B + kk);
            ldsm4(bfr[1], bW + 0 * TILE_B + kk + 16 * 144);
            ldsm4(afr[0], aW + 2 * TILE_B + kk);
            ldsm4(afr[1], aW + 2 * TILE_B + kk + 16 * 144);
#pragma unroll
            for (int mt = 0; mt < 2; mt++)
#pragma unroll
                for (int q = 0; q < 4; q++)
                    mma16816(acc[mt][q], afr[mt], bfr[q >> 1][q & 1], bfr[q >> 1][2 + (q & 1)]);
            ldsm4(afr[0], aW + 1 * TILE_B + kk);
            ldsm4(afr[1], aW + 1 * TILE_B + kk + 16 * 144);
#pragma unroll
            for (int mt = 0; mt < 2; mt++)
#pragma unroll
                for (int q = 0; q < 4; q++)
                    mma16816(acc[mt][q], afr[mt], bfr[q >> 1][q & 1], bfr[q >> 1][2 + (q & 1)]);
            ldsm4(bfr[0], bW + 1 * TILE_B + kk);
            ldsm4(bfr[1], bW + 1 * TILE_B + kk + 16 * 144);
#pragma unroll
            for (int mt = 0; mt < 2; mt++)
#pragma unroll
                for (int q = 0; q < 4; q++)
                    mma16816(acc[mt][q], afr[mt], bfr[q >> 1][q & 1], bfr[q >> 1][2 + (q & 1)]);
            ldsm4(afr[0], aW + 0 * TILE_B + kk);
            ldsm4(afr[1], aW + 0 * TILE_B + kk + 16 * 144);
#pragma unroll
            for (int mt = 0; mt < 2; mt++)
#pragma unroll
                for (int q = 0; q < 4; q++)
                    mma16816(acc[mt][q], afr[mt], bfr[q >> 1][q & 1], bfr[q >> 1][2 + (q & 1)]);
            ldsm4(bfr[0], bW + 2 * TILE_B + kk);
            ldsm4(bfr[1], bW + 2 * TILE_B + kk + 16 * 144);
#pragma unroll
            for (int mt = 0; mt < 2; mt++)
#pragma unroll
                for (int q = 0; q < 4; q++)
                    mma16816(acc[mt][q], afr[mt], bfr[q >> 1][q & 1], bfr[q >> 1][2 + (q & 1)]);
        }
        // ---- phase 2: main pass (0,0) ----
#pragma unroll
        for (int k16 = 0; k16 < 4; k16++) {
            uint32_t kk = (uint32_t)k16 * 32;
            uint32_t afr[2][4], bfr[2][4];
            ldsm4(bfr[0], bW + kk);
            ldsm4(bfr[1], bW + kk + 16 * 144);
            ldsm4(afr[0], aW + kk);
            ldsm4(afr[1], aW + kk + 16 * 144);
#pragma unroll
            for (int mt = 0; mt < 2; mt++)
#pragma unroll
                for (int q = 0; q < 4; q++)
                    mma16816(acc[mt][q], afr[mt], bfr[q >> 1][q & 1], bfr[q >> 1][2 + (q & 1)]);
        }
        // ---- bank chunk into running sum ----
#pragma unroll
        for (int a = 0; a < 2; a++)
#pragma unroll
            for (int b = 0; b < 4; b++)
#pragma unroll
                for (int c2 = 0; c2 < 4; c2++) {
                    run[a][b][c2] += acc[a][b][c2];
                    acc[a][b][c2] = 0.f;
                }
        stg ^= 1;
    }

    // ======================= epilogue =======================
    if (MODE == 2) {
#pragma unroll
        for (int mt = 0; mt < 2; mt++)
#pragma unroll
            for (int q = 0; q < 4; q++) {
                int n0 = nb * 128 + wn * 32 + q * 8 + 2 * (lane & 3);
                int rowa = wm * 32 + mt * 16 + (lane >> 2);
#pragma unroll
                for (int ri = 0; ri < 2; ri++) {
                    int rr = rowa + ri * 8;
                    int rg = rb * 128 + rr;
                    float p0 = sigf(run[mt][q][2 * ri]     + lin_b[n0]);
                    float p1 = sigf(run[mt][q][2 * ri + 1] + lin_b[n0 + 1]);
                    d_out[(rg * 31 + step + 1) * 256 + n0]     = p0;
                    d_out[(rg * 31 + step + 1) * 256 + n0 + 1] = p1;
                    __nv_bfloat16 s0[3], s1[3];
                    split3(p0, s0[0], s0[1], s0[2]);
                    split3(p1, s1[0], s1[1], s1[2]);
                    int chx = n0 >> 6, col = n0 & 63;
#pragma unroll
                    for (int sp = 0; sp < 3; sp++) {
                        __nv_bfloat162 v; v.x = s0[sp]; v.y = s1[sp];
                        *(__nv_bfloat162*)&g_prob[sp][rb][chx][rr * 64 + col] = v;
                    }
                }
            }
    } else {
        const int odd = lane & 1;
#pragma unroll
        for (int mt = 0; mt < 2; mt++)
#pragma unroll
            for (int q = 0; q < 4; q++) {
                float c0 = run[mt][q][0], c1 = run[mt][q][1];
                float c2 = run[mt][q][2], c3 = run[mt][q][3];
                float ex0 = __shfl_xor_sync(0xffffffffu, c0, 1);
                float ex1 = __shfl_xor_sync(0xffffffffu, c1, 1);
                float ex2 = __shfl_xor_sync(0xffffffffu, c2, 1);
                float ex3 = __shfl_xor_sync(0xffffffffu, c3, 1);
                float gi, gf, gg, go;
                int row128 = wm * 32 + mt * 16 + (lane >> 2);
                if (!odd) { gi = c0;  gf = c1;  gg = ex0; go = ex1; }
                else      { gi = ex2; gf = ex3; gg = c2;  go = c3;  row128 += 8; }
                int U = nb * 32 + wn * 8 + q * 2 + ((lane & 3) >> 1);
                const float* bi = &g_bias[layer][0][4 * U];
                const float* bh = &g_bias[layer][1][4 * U];
                int rg = rb * 128 + row128;
                float cold = g_cst[layer][rg * 256 + U];
                float cn = sigf((gf + bi[1]) + bh[1]) * cold
                         + sigf((gi + bi[0]) + bh[0]) * tanhf((gg + bi[2]) + bh[2]);
                g_cst[layer][rg * 256 + U] = cn;
                float h = sigf((go + bi[3]) + bh[3]) * tanhf(cn);
                __nv_bfloat16 s0, s1, s2;
                split3(h, s0, s1, s2);
                int off = row128 * 64 + (U & 63);
                int uc = U >> 6;
                g_hs[par ^ 1][layer][0][rb][uc][off] = s0;
                g_hs[par ^ 1][layer][1][rb][uc][off] = s1;
                g_hs[par ^ 1][layer][2][rb][uc][off] = s2;
            }
    }
}

// ---------------- argmax (first-max semantics) ----------------
__global__ void argmax_kernel(const float* __restrict__ d_probs, float* __restrict__ outs, int s) {
    int warp = (blockIdx.x * blockDim.x + threadIdx.x) >> 5;
    int lane = threadIdx.x & 31;
    if (warp >= BSZ) return;
    const float* row = d_probs + (warp * 31 + s + 1) * 256;
    float best = -1e30f; int bi = 0;
#pragma unroll
    for (int j = 0; j < 8; j++) {
        int c = lane + j * 32;
        float v = row[c];
        if (v > best) { best = v; bi = c; }
    }
#pragma unroll
    for (int off = 16; off; off >>= 1) {
        float ov = __shfl_xor_sync(0xffffffffu, best, off);
        int   oi = __shfl_xor_sync(0xffffffffu, bi, off);
        if (ov > best || (ov == best && oi < bi)) { best = ov; bi = oi; }
    }
    if (lane == 0) outs[warp * NSTEP + s] = (float)bi;
}

// ======================= launch =======================
extern "C" void kernel_launch(void* const* d_in, const int* in_sizes, int n_in,
                              void* d_out_v, int out_size)
{
    const float* tags = (const float*)d_in[2];
    const float* Wih0 = (const float*)d_in[13];
    const float* Whh0 = (const float*)d_in[14];
    const float* bih0 = (const float*)d_in[15];
    const float* bhh0 = (const float*)d_in[16];
    const float* Wih  = (const float*)d_in[17];
    const float* Whh  = (const float*)d_in[18];
    const float* bih  = (const float*)d_in[19];
    const float* bhh  = (const float*)d_in[20];
    const float* linW = (const float*)d_in[21];
    const float* linb = (const float*)d_in[22];
    float* d_out = (float*)d_out_v;

    cudaFuncSetAttribute(mma_kernel<0>, cudaFuncAttributeMaxDynamicSharedMemorySize, SMEM_TOTAL);
    cudaFuncSetAttribute(mma_kernel<1>, cudaFuncAttributeMaxDynamicSharedMemorySize, SMEM_TOTAL);
    cudaFuncSetAttribute(mma_kernel<2>, cudaFuncAttributeMaxDynamicSharedMemorySize, SMEM_TOTAL);

    bool has_outputs = (out_size >= PROBS_TOTAL + BSZ * NSTEP);

    {
        long total = 3L * BSZ * 256 + 3L * 3 * 32 * 4 * 8192 / 2
                   + (long)BSZ * 256 + (long)BSZ * 128 + 3 * 1024;
        k_setup<<<(unsigned)((total + 255) / 256), 256>>>(tags, bih0, bhh0, bih, bhh, d_out);
    }
    {
        int nw = 1024 * 640 + 2 * 1024 * 512 + 256 * 256;
        k_build_w<<<(nw + 255) / 256, 256>>>(Wih0, Whh0, Wih, Whh, linW);
    }

    for (int s = 0; s < NSTEP; s++) {
        int par = s & 1;
        mma_kernel<0><<<dim3(32, 8), 512, SMEM_TOTAL>>>(0, par, s, nullptr, d_out);
        mma_kernel<1><<<dim3(32, 8), 512, SMEM_TOTAL>>>(1, par, s, nullptr, d_out);
        mma_kernel<1><<<dim3(32, 8), 512, SMEM_TOTAL>>>(2, par, s, nullptr, d_out);
        mma_kernel<2><<<dim3(32, 2), 512, SMEM_TOTAL>>>(0, par, s, linb, d_out);
        if (has_outputs)
            argmax_kernel<<<(BSZ * 32 + 255) / 256, 256>>>(d_out, d_out + PROBS_TOTAL, s);
    }
}

// round 16
// speedup vs baseline: 1.1988x; 1.1988x over previous
#include <cuda_runtime.h>
#include <cuda_bf16.h>
#include <cstdint>
#include <math.h>

#define BSZ   4096
#define NSTEP 30
#define PROBS_STRIDE (31*256)
#define PROBS_TOTAL  (4096*31*256)

// ======================= device images (no allocs allowed) =======================
__device__ __align__(128) __nv_bfloat16 g_prob[3][32][4][8192];
__device__ __align__(128) __nv_bfloat16 g_tags[3][32][2][8192];
__device__ __align__(128) __nv_bfloat16 g_hs[2][3][3][32][4][8192];
__device__ __align__(128) __nv_bfloat16 g_w0[3][4][10][16384];
__device__ __align__(128) __nv_bfloat16 g_w12[2][3][4][8][16384];
__device__ __align__(128) __nv_bfloat16 g_wlin[3][4][16384];
__device__ float g_bias[3][2][1024];
__device__ float g_cst[3][BSZ*256];

// ======================= helpers =======================
__device__ __forceinline__ float sigf(float x) { return 1.0f / (1.0f + expf(-x)); }

__device__ __forceinline__ void split3(float x, __nv_bfloat16& a, __nv_bfloat16& b, __nv_bfloat16& c) {
    a = __float2bfloat16_rn(x);
    float r = x - __bfloat162float(a);
    b = __float2bfloat16_rn(r);
    float r2 = r - __bfloat162float(b);
    c = __float2bfloat16_rn(r2);
}

__device__ __forceinline__ uint32_t smem_u32(const void* p) {
    uint32_t a;
    asm("{ .reg .u64 t; cvta.to.shared.u64 t, %1; cvt.u32.u64 %0, t; }" : "=r"(a) : "l"(p));
    return a;
}

__device__ __forceinline__ void ldsm4(uint32_t* r, uint32_t addr) {
    asm volatile("ldmatrix.sync.aligned.m8n8.x4.shared.b16 {%0,%1,%2,%3}, [%4];"
                 : "=r"(r[0]), "=r"(r[1]), "=r"(r[2]), "=r"(r[3]) : "r"(addr));
}

__device__ __forceinline__ void mma16816(float* c, const uint32_t* a, uint32_t b0, uint32_t b1) {
    asm volatile(
        "mma.sync.aligned.m16n8k16.row.col.f32.bf16.bf16.f32 "
        "{%0,%1,%2,%3}, {%4,%5,%6,%7}, {%8,%9}, {%0,%1,%2,%3};"
        : "+f"(c[0]), "+f"(c[1]), "+f"(c[2]), "+f"(c[3])
        : "r"(a[0]), "r"(a[1]), "r"(a[2]), "r"(a[3]), "r"(b0), "r"(b1));
}

__device__ __forceinline__ void cpa16(uint32_t s, const char* g) {
    asm volatile("cp.async.cg.shared.global [%0], [%1], 16;" :: "r"(s), "l"(g));
}

// ======================= prologue kernels (2 launches) ==========
__global__ void k_setup(const float* __restrict__ tags,
                        const float* __restrict__ bih0, const float* __restrict__ bhh0,
                        const float* __restrict__ bih,  const float* __restrict__ bhh,
                        float* __restrict__ d_out) {
    long i = (long)blockIdx.x * blockDim.x + threadIdx.x;
    const long N1 = 3L * BSZ * 256;
    const long N2 = 3L * 3 * 32 * 4 * 8192 / 2;
    const long N3 = (long)BSZ * 256;
    const long N4 = (long)BSZ * 128;
    const long N5 = 3 * 1024;
    if (i < N1) { ((float*)g_cst)[i] = 0.f; return; }
    i -= N1;
    if (i < N2) { ((uint32_t*)g_hs[0])[i] = 0u; return; }
    i -= N2;
    if (i < N3) {
        int b = (int)(i >> 8), a = (int)(i & 255);
        float v = (a == 1) ? 1.0f : 0.0f;
        d_out[b * PROBS_STRIDE + a] = v;
        int rb = b >> 7, row = b & 127, ch = a >> 6, col = a & 63;
        int off = row * 64 + col;
        g_prob[0][rb][ch][off] = __float2bfloat16_rn(v);
        g_prob[1][rb][ch][off] = __float2bfloat16_rn(0.f);
        g_prob[2][rb][ch][off] = __float2bfloat16_rn(0.f);
        return;
    }
    i -= N3;
    if (i < N4) {
        int b = (int)(i >> 7), k = (int)(i & 127);
        __nv_bfloat16 s1, s2, s3;
        split3(tags[b * 128 + k], s1, s2, s3);
        int rb = b >> 7, row = b & 127, ch = k >> 6, col = k & 63;
        int off = row * 64 + col;
        g_tags[0][rb][ch][off] = s1;
        g_tags[1][rb][ch][off] = s2;
        g_tags[2][rb][ch][off] = s3;
        return;
    }
    i -= N4;
    if (i < N5) {
        int l = (int)(i >> 10), n = (int)(i & 1023);
        int u = n >> 2, g = n & 3;
        int src = g * 256 + u;
        if (l == 0) {
            g_bias[0][0][n] = bih0[src];
            g_bias[0][1][n] = bhh0[src];
        } else {
            g_bias[l][0][n] = bih[(l - 1) * 1024 + src];
            g_bias[l][1][n] = bhh[(l - 1) * 1024 + src];
        }
    }
}

__global__ void k_build_w(const float* __restrict__ Wih0, const float* __restrict__ Whh0,
                          const float* __restrict__ Wih,  const float* __restrict__ Whh,
                          const float* __restrict__ linW) {
    int i = blockIdx.x * blockDim.x + threadIdx.x;
    if (i < 1024 * 640) {
        int n = i / 640, k = i % 640;
        int u = n >> 2, g = n & 3;
        int src = g * 256 + u;
        float v = (k < 384) ? Wih0[src * 384 + k] : Whh0[src * 256 + (k - 384)];
        __nv_bfloat16 s1, s2, s3;
        split3(v, s1, s2, s3);
        int nb = n >> 8, row = n & 255, ch = k >> 6, col = k & 63;
        int off = row * 64 + col;
        g_w0[0][nb][ch][off] = s1;
        g_w0[1][nb][ch][off] = s2;
        g_w0[2][nb][ch][off] = s3;
        return;
    }
    i -= 1024 * 640;
    if (i < 2 * 1024 * 512) {
        int l = i / (1024 * 512);
        int r = i % (1024 * 512);
        int n = r / 512, k = r % 512;
        int u = n >> 2, g = n & 3;
        int src = g * 256 + u;
        float v = (k < 256) ? Wih[(l * 1024 + src) * 256 + k] : Whh[(l * 1024 + src) * 256 + (k - 256)];
        __nv_bfloat16 s1, s2, s3;
        split3(v, s1, s2, s3);
        int nb = n >> 8, row = n & 255, ch = k >> 6, col = k & 63;
        int off = row * 64 + col;
        g_w12[l][0][nb][ch][off] = s1;
        g_w12[l][1][nb][ch][off] = s2;
        g_w12[l][2][nb][ch][off] = s3;
        return;
    }
    i -= 2 * 1024 * 512;
    if (i < 256 * 256) {
        int n = i >> 8, k = i & 255;
        __nv_bfloat16 s1, s2, s3;
        split3(linW[n * 256 + k], s1, s2, s3);
        int ch = k >> 6, col = k & 63;
        int off = n * 64 + col;
        g_wlin[0][ch][off] = s1;
        g_wlin[1][ch][off] = s2;
        g_wlin[2][ch][off] = s3;
    }
}

// ======================= fused mma.sync GEMM (bf16 6-pass, fp32-faithful) =======================
// CTA tile 128 rows x 64 gate-cols; warp tile 32x32 (4x2 warps); 2 CTAs/SM.
// R13 skeleton + split correction/main loops + B-fragment k16 double-buffer.
#define NPASS 6
__device__ __constant__ int PAI[NPASS] = {2, 1, 0, 1, 0, 0};
__device__ __constant__ int PBI[NPASS] = {0, 1, 2, 0, 1, 0};

#define ATILE_B 18432              // 128 x 144B
#define BTILE_B 9216               // 64 x 144B
#define STAGE_B (ATILE_B + BTILE_B)  // 27648
#define NSTAGE  3
#define RING_B  (NSTAGE*STAGE_B)     // 82944
#define MAXNCH  60
#define SMEM_TOTAL (RING_B + 2*MAXNCH*8)   // 83904

template<int MODE>
__device__ __forceinline__ const char* a_chunk(int ai, int c, int rb, int layer, int par) {
    if (MODE == 0) {
        if (c < 4) return (const char*)&g_prob[ai][rb][c][0];
        if (c < 6) return (const char*)&g_tags[ai][rb][c - 4][0];
        return (const char*)&g_hs[par][0][ai][rb][c - 6][0];
    } else if (MODE == 1) {
        if (c < 4) return (const char*)&g_hs[par ^ 1][layer - 1][ai][rb][c][0];
        return (const char*)&g_hs[par][layer][ai][rb][c - 4][0];
    } else {
        return (const char*)&g_hs[par ^ 1][2][ai][rb][c][0];
    }
}

template<int MODE>
__device__ __forceinline__ const char* b_chunk(int bi, int c, int nb, int layer) {
    if (MODE == 0)      return (const char*)((const uint4*)&g_w0[bi][nb >> 2][c][0] + (nb & 3) * 512);
    else if (MODE == 1) return (const char*)((const uint4*)&g_w12[layer - 1][bi][nb >> 2][c][0] + (nb & 3) * 512);
    else                return (const char*)((const uint4*)&g_wlin[bi][c][0] + nb * 512);
}

template<int MODE>
__global__ __launch_bounds__(256, 2) void mma_kernel(
    int layer, int par, int step, const float* __restrict__ lin_b, float* __restrict__ d_out)
{
    extern __shared__ __align__(16) char smem[];
    const int KC  = (MODE == 0) ? 10 : (MODE == 1 ? 8 : 4);
    const int NCH = NPASS * KC;
    const int MAIN_START = (NPASS - 1) * KC;
    const int rb = blockIdx.x, nb = blockIdx.y;
    const int tid = threadIdx.x;
    const int wid = tid >> 5, lane = tid & 31;
    const int wm = wid >> 1, wn = wid & 1;      // 4 (m) x 2 (n) warps; warp tile 32x32
    uint32_t sb = smem_u32(smem);

    const char** Atab = (const char**)(smem + RING_B);
    const char** Btab = (const char**)(smem + RING_B + MAXNCH * 8);

    if (tid < NCH) {
        int pass = tid / KC, c = tid - pass * KC;
        Atab[tid] = a_chunk<MODE>(PAI[pass], c, rb, layer, par);
        Btab[tid] = b_chunk<MODE>(PBI[pass], c, nb, layer);
    }

    uint32_t goff[4], soffA[4], soffB[2];
#pragma unroll
    for (int i = 0; i < 4; i++) {
        int idx = tid + (i << 8);
        goff[i]  = (uint32_t)idx * 16u;
        soffA[i] = (idx >> 3) * 144 + (idx & 7) * 16;
    }
#pragma unroll
    for (int i = 0; i < 2; i++) {
        int idx = tid + (i << 8);
        soffB[i] = (idx >> 3) * 144 + (idx & 7) * 16;
    }

    float acc[2][4][4];
    float run[2][4][4];
#pragma unroll
    for (int a = 0; a < 2; a++)
#pragma unroll
        for (int b = 0; b < 4; b++)
#pragma unroll
            for (int c = 0; c < 4; c++) { acc[a][b][c] = 0.f; run[a][b][c] = 0.f; }

    __syncthreads();   // table visible

    auto issue = [&](int ch, int buf) {
        const char* Ag = Atab[ch];
        const char* Bg = Btab[ch];
        uint32_t Ab = sb + buf * STAGE_B;
        uint32_t Bb = Ab + ATILE_B;
#pragma unroll
        for (int i = 0; i < 4; i++) cpa16(Ab + soffA[i], Ag + goff[i]);
#pragma unroll
        for (int i = 0; i < 2; i++) cpa16(Bb + soffB[i], Bg + goff[i]);
        asm volatile("cp.async.commit_group;" ::: "memory");
    };

    const uint32_t lane_off = (lane & 15) * 144 + (lane >> 4) * 16;

    // compute one resident chunk from buffer `buf` (B frags double-buffered over k16)
    auto compute = [&](int buf) {
        uint32_t Abase = sb + buf * STAGE_B;
        uint32_t Bbase = Abase + ATILE_B;
        uint32_t aoff = Abase + wm * (32 * 144) + lane_off;
        uint32_t boff = Bbase + wn * (32 * 144) + lane_off;
        uint32_t bfr[2][2][4];
        ldsm4(bfr[0][0], boff);
        ldsm4(bfr[0][1], boff + 16 * 144);
#pragma unroll
        for (int k16 = 0; k16 < 4; k16++) {
            const int cur = k16 & 1;
            if (k16 < 3) {
                ldsm4(bfr[cur ^ 1][0], boff + (k16 + 1) * 32);
                ldsm4(bfr[cur ^ 1][1], boff + (k16 + 1) * 32 + 16 * 144);
            }
            uint32_t afr[2][4];
#pragma unroll
            for (int mt = 0; mt < 2; mt++)
                ldsm4(afr[mt], aoff + mt * (16 * 144) + k16 * 32);
#pragma unroll
            for (int mt = 0; mt < 2; mt++)
#pragma unroll
                for (int q = 0; q < 4; q++)
                    mma16816(acc[mt][q], afr[mt],
                             bfr[cur][q >> 1][q & 1], bfr[cur][q >> 1][2 + (q & 1)]);
        }
    };

    issue(0, 0);
    issue(1, 1);

    int buf = 0;
    // ---- correction passes: chunks 0 .. MAIN_START-1 (no banking) ----
    for (int ch = 0; ch < MAIN_START; ch++) {
        asm volatile("cp.async.wait_group 1;" ::: "memory");
        __syncthreads();
        int nbuf = buf + 2; if (nbuf >= NSTAGE) nbuf -= NSTAGE;
        issue(ch + 2, nbuf);
        compute(buf);
        if (++buf >= NSTAGE) buf = 0;
    }
    // bank correction total (run was 0 -> run = acc), restart acc
#pragma unroll
    for (int a = 0; a < 2; a++)
#pragma unroll
        for (int b = 0; b < 4; b++)
#pragma unroll
            for (int c2 = 0; c2 < 4; c2++) { run[a][b][c2] += acc[a][b][c2]; acc[a][b][c2] = 0.f; }

    // ---- main pass: chunks MAIN_START .. NCH-1 (bank each chunk) ----
    for (int ch = MAIN_START; ch < NCH; ch++) {
        if (ch + 1 < NCH) { asm volatile("cp.async.wait_group 1;" ::: "memory"); }
        else              { asm volatile("cp.async.wait_group 0;" ::: "memory"); }
        __syncthreads();
        if (ch + 2 < NCH) {
            int nbuf = buf + 2; if (nbuf >= NSTAGE) nbuf -= NSTAGE;
            issue(ch + 2, nbuf);
        }
        compute(buf);
#pragma unroll
        for (int a = 0; a < 2; a++)
#pragma unroll
            for (int b = 0; b < 4; b++)
#pragma unroll
                for (int c2 = 0; c2 < 4; c2++) { run[a][b][c2] += acc[a][b][c2]; acc[a][b][c2] = 0.f; }
        if (++buf >= NSTAGE) buf = 0;
    }

    // ======================= epilogue =======================
    if (MODE == 2) {
#pragma unroll
        for (int mt = 0; mt < 2; mt++)
#pragma unroll
            for (int q = 0; q < 4; q++) {
                int n0 = nb * 64 + wn * 32 + q * 8 + 2 * (lane & 3);
                int rowa = wm * 32 + mt * 16 + (lane >> 2);
#pragma unroll
                for (int ri = 0; ri < 2; ri++) {
                    int rr = rowa + ri * 8;
                    int rg = rb * 128 + rr;
                    float p0 = sigf(run[mt][q][2 * ri]     + lin_b[n0]);
                    float p1 = sigf(run[mt][q][2 * ri + 1] + lin_b[n0 + 1]);
                    d_out[(rg * 31 + step + 1) * 256 + n0]     = p0;
                    d_out[(rg * 31 + step + 1) * 256 + n0 + 1] = p1;
                    __nv_bfloat16 s0[3], s1[3];
                    split3(p0, s0[0], s0[1], s0[2]);
                    split3(p1, s1[0], s1[1], s1[2]);
                    int chx = n0 >> 6, col = n0 & 63;
#pragma unroll
                    for (int sp = 0; sp < 3; sp++) {
                        __nv_bfloat162 v; v.x = s0[sp]; v.y = s1[sp];
                        *(__nv_bfloat162*)&g_prob[sp][rb][chx][rr * 64 + col] = v;
                    }
                }
            }
    } else {
        const int odd = lane & 1;
#pragma unroll
        for (int mt = 0; mt < 2; mt++)
#pragma unroll
            for (int q = 0; q < 4; q++) {
                float c0 = run[mt][q][0], c1 = run[mt][q][1];
                float c2 = run[mt][q][2], c3 = run[mt][q][3];
                float ex0 = __shfl_xor_sync(0xffffffffu, c0, 1);
                float ex1 = __shfl_xor_sync(0xffffffffu, c1, 1);
                float ex2 = __shfl_xor_sync(0xffffffffu, c2, 1);
                float ex3 = __shfl_xor_sync(0xffffffffu, c3, 1);
                float gi, gf, gg, go;
                int row128 = wm * 32 + mt * 16 + (lane >> 2);
                if (!odd) { gi = c0;  gf = c1;  gg = ex0; go = ex1; }
                else      { gi = ex2; gf = ex3; gg = c2;  go = c3;  row128 += 8; }
                int U = nb * 16 + wn * 8 + q * 2 + ((lane & 3) >> 1);
                const float* bi = &g_bias[layer][0][4 * U];
                const float* bh = &g_bias[layer][1][4 * U];
                int rg = rb * 128 + row128;
                float cold = g_cst[layer][rg * 256 + U];
                float cn = sigf((gf + bi[1]) + bh[1]) * cold
                         + sigf((gi + bi[0]) + bh[0]) * tanhf((gg + bi[2]) + bh[2]);
                g_cst[layer][rg * 256 + U] = cn;
                float h = sigf((go + bi[3]) + bh[3]) * tanhf(cn);
                __nv_bfloat16 s0, s1, s2;
                split3(h, s0, s1, s2);
                int off = row128 * 64 + (U & 63);
                int uc = U >> 6;
                g_hs[par ^ 1][layer][0][rb][uc][off] = s0;
                g_hs[par ^ 1][layer][1][rb][uc][off] = s1;
                g_hs[par ^ 1][layer][2][rb][uc][off] = s2;
            }
    }
}

// ---------------- argmax (first-max semantics) ----------------
__global__ void argmax_kernel(const float* __restrict__ d_probs, float* __restrict__ outs, int s) {
    int warp = (blockIdx.x * blockDim.x + threadIdx.x) >> 5;
    int lane = threadIdx.x & 31;
    if (warp >= BSZ) return;
    const float* row = d_probs + (warp * 31 + s + 1) * 256;
    float best = -1e30f; int bi = 0;
#pragma unroll
    for (int j = 0; j < 8; j++) {
        int c = lane + j * 32;
        float v = row[c];
        if (v > best) { best = v; bi = c; }
    }
#pragma unroll
    for (int off = 16; off; off >>= 1) {
        float ov = __shfl_xor_sync(0xffffffffu, best, off);
        int   oi = __shfl_xor_sync(0xffffffffu, bi, off);
        if (ov > best || (ov == best && oi < bi)) { best = ov; bi = oi; }
    }
    if (lane == 0) outs[warp * NSTEP + s] = (float)bi;
}

// ======================= launch =======================
extern "C" void kernel_launch(void* const* d_in, const int* in_sizes, int n_in,
                              void* d_out_v, int out_size)
{
    const float* tags = (const float*)d_in[2];
    const float* Wih0 = (const float*)d_in[13];
    const float* Whh0 = (const float*)d_in[14];
    const float* bih0 = (const float*)d_in[15];
    const float* bhh0 = (const float*)d_in[16];
    const float* Wih  = (const float*)d_in[17];
    const float* Whh  = (const float*)d_in[18];
    const float* bih  = (const float*)d_in[19];
    const float* bhh  = (const float*)d_in[20];
    const float* linW = (const float*)d_in[21];
    const float* linb = (const float*)d_in[22];
    float* d_out = (float*)d_out_v;

    cudaFuncSetAttribute(mma_kernel<0>, cudaFuncAttributeMaxDynamicSharedMemorySize, SMEM_TOTAL);
    cudaFuncSetAttribute(mma_kernel<1>, cudaFuncAttributeMaxDynamicSharedMemorySize, SMEM_TOTAL);
    cudaFuncSetAttribute(mma_kernel<2>, cudaFuncAttributeMaxDynamicSharedMemorySize, SMEM_TOTAL);

    bool has_outputs = (out_size >= PROBS_TOTAL + BSZ * NSTEP);

    {
        long total = 3L * BSZ * 256 + 3L * 3 * 32 * 4 * 8192 / 2
                   + (long)BSZ * 256 + (long)BSZ * 128 + 3 * 1024;
        k_setup<<<(unsigned)((total + 255) / 256), 256>>>(tags, bih0, bhh0, bih, bhh, d_out);
    }
    {
        int nw = 1024 * 640 + 2 * 1024 * 512 + 256 * 256;
        k_build_w<<<(nw + 255) / 256, 256>>>(Wih0, Whh0, Wih, Whh, linW);
    }

    for (int s = 0; s < NSTEP; s++) {
        int par = s & 1;
        mma_kernel<0><<<dim3(32, 16), 256, SMEM_TOTAL>>>(0, par, s, nullptr, d_out);
        mma_kernel<1><<<dim3(32, 16), 256, SMEM_TOTAL>>>(1, par, s, nullptr, d_out);
        mma_kernel<1><<<dim3(32, 16), 256, SMEM_TOTAL>>>(2, par, s, nullptr, d_out);
        mma_kernel<2><<<dim3(32, 4), 256, SMEM_TOTAL>>>(0, par, s, linb, d_out);
        if (has_outputs)
            argmax_kernel<<<(BSZ * 32 + 255) / 256, 256>>>(d_out, d_out + PROBS_TOTAL, s);
    }
}

// round 17
// speedup vs baseline: 1.2571x; 1.0487x over previous
#include <cuda_runtime.h>
#include <cuda_bf16.h>
#include <cstdint>
#include <math.h>

#define BSZ   4096
#define NSTEP 30
#define PROBS_STRIDE (31*256)
#define PROBS_TOTAL  (4096*31*256)

// ======================= device images (no allocs allowed) =======================
__device__ __align__(128) __nv_bfloat16 g_prob[3][32][4][8192];
__device__ __align__(128) __nv_bfloat16 g_hs[2][3][3][32][4][8192];
__device__ __align__(128) __nv_bfloat16 g_w0[3][4][8][16384];    // tags columns removed (K=512)
__device__ __align__(128) __nv_bfloat16 g_w12[2][3][4][8][16384];
__device__ __align__(128) __nv_bfloat16 g_wlin[3][4][16384];
__device__ float g_bias[3][2][1024];
__device__ float g_cst[3][BSZ*256];
__device__ float g_pre0[BSZ*1024];          // tags @ Wtags^T, gate-reordered (fp32, one-time)

// ======================= helpers =======================
__device__ __forceinline__ float sigf(float x) { return 1.0f / (1.0f + expf(-x)); }

__device__ __forceinline__ void split3(float x, __nv_bfloat16& a, __nv_bfloat16& b, __nv_bfloat16& c) {
    a = __float2bfloat16_rn(x);
    float r = x - __bfloat162float(a);
    b = __float2bfloat16_rn(r);
    float r2 = r - __bfloat162float(b);
    c = __float2bfloat16_rn(r2);
}

__device__ __forceinline__ uint32_t smem_u32(const void* p) {
    uint32_t a;
    asm("{ .reg .u64 t; cvta.to.shared.u64 t, %1; cvt.u32.u64 %0, t; }" : "=r"(a) : "l"(p));
    return a;
}

__device__ __forceinline__ void ldsm4(uint32_t* r, uint32_t addr) {
    asm volatile("ldmatrix.sync.aligned.m8n8.x4.shared.b16 {%0,%1,%2,%3}, [%4];"
                 : "=r"(r[0]), "=r"(r[1]), "=r"(r[2]), "=r"(r[3]) : "r"(addr));
}

__device__ __forceinline__ void mma16816(float* c, const uint32_t* a, uint32_t b0, uint32_t b1) {
    asm volatile(
        "mma.sync.aligned.m16n8k16.row.col.f32.bf16.bf16.f32 "
        "{%0,%1,%2,%3}, {%4,%5,%6,%7}, {%8,%9}, {%0,%1,%2,%3};"
        : "+f"(c[0]), "+f"(c[1]), "+f"(c[2]), "+f"(c[3])
        : "r"(a[0]), "r"(a[1]), "r"(a[2]), "r"(a[3]), "r"(b0), "r"(b1));
}

__device__ __forceinline__ void cpa16(uint32_t s, const char* g) {
    asm volatile("cp.async.cg.shared.global [%0], [%1], 16;" :: "r"(s), "l"(g));
}

// ======================= prologue kernels (3 launches) ==========
__global__ void k_setup(const float* __restrict__ bih0, const float* __restrict__ bhh0,
                        const float* __restrict__ bih,  const float* __restrict__ bhh,
                        float* __restrict__ d_out) {
    long i = (long)blockIdx.x * blockDim.x + threadIdx.x;
    const long N1 = 3L * BSZ * 256;
    const long N2 = 3L * 3 * 32 * 4 * 8192 / 2;
    const long N3 = (long)BSZ * 256;
    const long N5 = 3 * 1024;
    if (i < N1) { ((float*)g_cst)[i] = 0.f; return; }
    i -= N1;
    if (i < N2) { ((uint32_t*)g_hs[0])[i] = 0u; return; }
    i -= N2;
    if (i < N3) {
        int b = (int)(i >> 8), a = (int)(i & 255);
        float v = (a == 1) ? 1.0f : 0.0f;
        d_out[b * PROBS_STRIDE + a] = v;
        int rb = b >> 7, row = b & 127, ch = a >> 6, col = a & 63;
        int off = row * 64 + col;
        g_prob[0][rb][ch][off] = __float2bfloat16_rn(v);
        g_prob[1][rb][ch][off] = __float2bfloat16_rn(0.f);
        g_prob[2][rb][ch][off] = __float2bfloat16_rn(0.f);
        return;
    }
    i -= N3;
    if (i < N5) {
        int l = (int)(i >> 10), n = (int)(i & 1023);
        int u = n >> 2, g = n & 3;
        int src = g * 256 + u;
        if (l == 0) {
            g_bias[0][0][n] = bih0[src];
            g_bias[0][1][n] = bhh0[src];
        } else {
            g_bias[l][0][n] = bih[(l - 1) * 1024 + src];
            g_bias[l][1][n] = bhh[(l - 1) * 1024 + src];
        }
    }
}

__global__ void k_build_w(const float* __restrict__ Wih0, const float* __restrict__ Whh0,
                          const float* __restrict__ Wih,  const float* __restrict__ Whh,
                          const float* __restrict__ linW) {
    int i = blockIdx.x * blockDim.x + threadIdx.x;
    if (i < 1024 * 512) {                       // layer0: prob part (k<256) + hh part
        int n = i >> 9, k = i & 511;
        int u = n >> 2, g = n & 3;
        int src = g * 256 + u;
        float v = (k < 256) ? Wih0[src * 384 + k] : Whh0[src * 256 + (k - 256)];
        __nv_bfloat16 s1, s2, s3;
        split3(v, s1, s2, s3);
        int nb = n >> 8, row = n & 255, ch = k >> 6, col = k & 63;
        int off = row * 64 + col;
        g_w0[0][nb][ch][off] = s1;
        g_w0[1][nb][ch][off] = s2;
        g_w0[2][nb][ch][off] = s3;
        return;
    }
    i -= 1024 * 512;
    if (i < 2 * 1024 * 512) {
        int l = i / (1024 * 512);
        int r = i % (1024 * 512);
        int n = r >> 9, k = r & 511;
        int u = n >> 2, g = n & 3;
        int src = g * 256 + u;
        float v = (k < 256) ? Wih[(l * 1024 + src) * 256 + k] : Whh[(l * 1024 + src) * 256 + (k - 256)];
        __nv_bfloat16 s1, s2, s3;
        split3(v, s1, s2, s3);
        int nb = n >> 8, row = n & 255, ch = k >> 6, col = k & 63;
        int off = row * 64 + col;
        g_w12[l][0][nb][ch][off] = s1;
        g_w12[l][1][nb][ch][off] = s2;
        g_w12[l][2][nb][ch][off] = s3;
        return;
    }
    i -= 2 * 1024 * 512;
    if (i < 256 * 256) {
        int n = i >> 8, k = i & 255;
        __nv_bfloat16 s1, s2, s3;
        split3(linW[n * 256 + k], s1, s2, s3);
        int ch = k >> 6, col = k & 63;
        int off = n * 64 + col;
        g_wlin[0][ch][off] = s1;
        g_wlin[1][ch][off] = s2;
        g_wlin[2][ch][off] = s3;
    }
}

// pre0[r][n] = sum_k tags[r][k] * Wih0[src(n)][256+k]  (fp32, gate-reordered n=4u+g)
__global__ __launch_bounds__(256) void k_pre0(const float* __restrict__ tags,
                                              const float* __restrict__ Wih0) {
    __shared__ float As[16][68];
    __shared__ float Bs[16][68];
    int tid = threadIdx.x;
    int tx = tid & 15, ty = tid >> 4;
    int r0 = blockIdx.x * 64, n0 = blockIdx.y * 64;
    float acc[4][4];
#pragma unroll
    for (int i = 0; i < 4; i++)
#pragma unroll
        for (int j = 0; j < 4; j++) acc[i][j] = 0.f;
    for (int k0 = 0; k0 < 128; k0 += 16) {
#pragma unroll
        for (int it = 0; it < 4; it++) {
            int i = it * 256 + tid; int r = i >> 4, k = i & 15;
            As[k][r] = tags[(r0 + r) * 128 + k0 + k];
        }
#pragma unroll
        for (int it = 0; it < 4; it++) {
            int i = it * 256 + tid; int c = i >> 4, k = i & 15;
            int n = n0 + c, u = n >> 2, g = n & 3;
            Bs[k][c] = Wih0[(g * 256 + u) * 384 + 256 + k0 + k];
        }
        __syncthreads();
#pragma unroll
        for (int k = 0; k < 16; k++) {
            float a[4], b[4];
            *(float4*)a = *(const float4*)&As[k][ty * 4];
            *(float4*)b = *(const float4*)&Bs[k][tx * 4];
#pragma unroll
            for (int i = 0; i < 4; i++)
#pragma unroll
                for (int j = 0; j < 4; j++) acc[i][j] += a[i] * b[j];
        }
        __syncthreads();
    }
#pragma unroll
    for (int i = 0; i < 4; i++)
#pragma unroll
        for (int j = 0; j < 4; j++)
            g_pre0[(r0 + ty * 4 + i) * 1024 + n0 + tx * 4 + j] = acc[i][j];
}

// ======================= fused mma.sync GEMM (bf16 6-pass, fp32-faithful) =======================
// CTA tile 128 rows x 64 gate-cols; warp tile 32x32 (4x2 warps); 2 CTAs/SM.
#define NPASS 6
__device__ __constant__ int PAI[NPASS] = {2, 1, 0, 1, 0, 0};
__device__ __constant__ int PBI[NPASS] = {0, 1, 2, 0, 1, 0};

#define ATILE_B 18432
#define BTILE_B 9216
#define STAGE_B (ATILE_B + BTILE_B)
#define NSTAGE  3
#define RING_B  (NSTAGE*STAGE_B)
#define MAXNCH  48
#define SMEM_TOTAL (RING_B + 2*MAXNCH*8)

template<int MODE>
__device__ __forceinline__ const char* a_chunk(int ai, int c, int rb, int layer, int par) {
    if (MODE == 0) {
        if (c < 4) return (const char*)&g_prob[ai][rb][c][0];
        return (const char*)&g_hs[par][0][ai][rb][c - 4][0];
    } else if (MODE == 1) {
        if (c < 4) return (const char*)&g_hs[par ^ 1][layer - 1][ai][rb][c][0];
        return (const char*)&g_hs[par][layer][ai][rb][c - 4][0];
    } else {
        return (const char*)&g_hs[par ^ 1][2][ai][rb][c][0];
    }
}

template<int MODE>
__device__ __forceinline__ const char* b_chunk(int bi, int c, int nb, int layer) {
    if (MODE == 0)      return (const char*)((const uint4*)&g_w0[bi][nb >> 2][c][0] + (nb & 3) * 512);
    else if (MODE == 1) return (const char*)((const uint4*)&g_w12[layer - 1][bi][nb >> 2][c][0] + (nb & 3) * 512);
    else                return (const char*)((const uint4*)&g_wlin[bi][c][0] + nb * 512);
}

template<int MODE>
__global__ __launch_bounds__(256, 2) void mma_kernel(
    int layer, int par, int step, const float* __restrict__ lin_b, float* __restrict__ d_out)
{
    extern __shared__ __align__(16) char smem[];
    const int KC  = (MODE == 2) ? 4 : 8;
    const int NCH = NPASS * KC;
    const int MAIN_START = (NPASS - 1) * KC;
    const int rb = blockIdx.x, nb = blockIdx.y;
    const int tid = threadIdx.x;
    const int wid = tid >> 5, lane = tid & 31;
    const int wm = wid >> 1, wn = wid & 1;
    uint32_t sb = smem_u32(smem);

    const char** Atab = (const char**)(smem + RING_B);
    const char** Btab = (const char**)(smem + RING_B + MAXNCH * 8);

    if (tid < NCH) {
        int pass = tid / KC, c = tid - pass * KC;
        Atab[tid] = a_chunk<MODE>(PAI[pass], c, rb, layer, par);
        Btab[tid] = b_chunk<MODE>(PBI[pass], c, nb, layer);
    }

    uint32_t goff[4], soffA[4], soffB[2];
#pragma unroll
    for (int i = 0; i < 4; i++) {
        int idx = tid + (i << 8);
        goff[i]  = (uint32_t)idx * 16u;
        soffA[i] = (idx >> 3) * 144 + (idx & 7) * 16;
    }
#pragma unroll
    for (int i = 0; i < 2; i++) {
        int idx = tid + (i << 8);
        soffB[i] = (idx >> 3) * 144 + (idx & 7) * 16;
    }

    float acc[2][4][4];
    float run[2][4][4];
#pragma unroll
    for (int a = 0; a < 2; a++)
#pragma unroll
        for (int b = 0; b < 4; b++)
#pragma unroll
            for (int c = 0; c < 4; c++) { acc[a][b][c] = 0.f; run[a][b][c] = 0.f; }

    __syncthreads();

    auto issue = [&](int ch, int buf) {
        const char* Ag = Atab[ch];
        const char* Bg = Btab[ch];
        uint32_t Ab = sb + buf * STAGE_B;
        uint32_t Bb = Ab + ATILE_B;
#pragma unroll
        for (int i = 0; i < 4; i++) cpa16(Ab + soffA[i], Ag + goff[i]);
#pragma unroll
        for (int i = 0; i < 2; i++) cpa16(Bb + soffB[i], Bg + goff[i]);
        asm volatile("cp.async.commit_group;" ::: "memory");
    };

    const uint32_t lane_off = (lane & 15) * 144 + (lane >> 4) * 16;

    auto compute = [&](int buf) {
        uint32_t Abase = sb + buf * STAGE_B;
        uint32_t Bbase = Abase + ATILE_B;
        uint32_t aoff = Abase + wm * (32 * 144) + lane_off;
        uint32_t boff = Bbase + wn * (32 * 144) + lane_off;
        uint32_t bfr[2][2][4];
        ldsm4(bfr[0][0], boff);
        ldsm4(bfr[0][1], boff + 16 * 144);
#pragma unroll
        for (int k16 = 0; k16 < 4; k16++) {
            const int cur = k16 & 1;
            if (k16 < 3) {
                ldsm4(bfr[cur ^ 1][0], boff + (k16 + 1) * 32);
                ldsm4(bfr[cur ^ 1][1], boff + (k16 + 1) * 32 + 16 * 144);
            }
            uint32_t afr[2][4];
#pragma unroll
            for (int mt = 0; mt < 2; mt++)
                ldsm4(afr[mt], aoff + mt * (16 * 144) + k16 * 32);
#pragma unroll
            for (int mt = 0; mt < 2; mt++)
#pragma unroll
                for (int q = 0; q < 4; q++)
                    mma16816(acc[mt][q], afr[mt],
                             bfr[cur][q >> 1][q & 1], bfr[cur][q >> 1][2 + (q & 1)]);
        }
    };

    issue(0, 0);
    issue(1, 1);

    int buf = 0;
    for (int ch = 0; ch < MAIN_START; ch++) {
        asm volatile("cp.async.wait_group 1;" ::: "memory");
        __syncthreads();
        int nbuf = buf + 2; if (nbuf >= NSTAGE) nbuf -= NSTAGE;
        issue(ch + 2, nbuf);
        compute(buf);
        if (++buf >= NSTAGE) buf = 0;
    }
#pragma unroll
    for (int a = 0; a < 2; a++)
#pragma unroll
        for (int b = 0; b < 4; b++)
#pragma unroll
            for (int c2 = 0; c2 < 4; c2++) { run[a][b][c2] += acc[a][b][c2]; acc[a][b][c2] = 0.f; }

    for (int ch = MAIN_START; ch < NCH; ch++) {
        if (ch + 1 < NCH) { asm volatile("cp.async.wait_group 1;" ::: "memory"); }
        else              { asm volatile("cp.async.wait_group 0;" ::: "memory"); }
        __syncthreads();
        if (ch + 2 < NCH) {
            int nbuf = buf + 2; if (nbuf >= NSTAGE) nbuf -= NSTAGE;
            issue(ch + 2, nbuf);
        }
        compute(buf);
#pragma unroll
        for (int a = 0; a < 2; a++)
#pragma unroll
            for (int b = 0; b < 4; b++)
#pragma unroll
                for (int c2 = 0; c2 < 4; c2++) { run[a][b][c2] += acc[a][b][c2]; acc[a][b][c2] = 0.f; }
        if (++buf >= NSTAGE) buf = 0;
    }

    // ======================= epilogue =======================
    if (MODE == 2) {
#pragma unroll
        for (int mt = 0; mt < 2; mt++)
#pragma unroll
            for (int q = 0; q < 4; q++) {
                int n0 = nb * 64 + wn * 32 + q * 8 + 2 * (lane & 3);
                int rowa = wm * 32 + mt * 16 + (lane >> 2);
#pragma unroll
                for (int ri = 0; ri < 2; ri++) {
                    int rr = rowa + ri * 8;
                    int rg = rb * 128 + rr;
                    float p0 = sigf(run[mt][q][2 * ri]     + lin_b[n0]);
                    float p1 = sigf(run[mt][q][2 * ri + 1] + lin_b[n0 + 1]);
                    d_out[(rg * 31 + step + 1) * 256 + n0]     = p0;
                    d_out[(rg * 31 + step + 1) * 256 + n0 + 1] = p1;
                    __nv_bfloat16 s0[3], s1[3];
                    split3(p0, s0[0], s0[1], s0[2]);
                    split3(p1, s1[0], s1[1], s1[2]);
                    int chx = n0 >> 6, col = n0 & 63;
#pragma unroll
                    for (int sp = 0; sp < 3; sp++) {
                        __nv_bfloat162 v; v.x = s0[sp]; v.y = s1[sp];
                        *(__nv_bfloat162*)&g_prob[sp][rb][chx][rr * 64 + col] = v;
                    }
                }
            }
    } else {
        const int odd = lane & 1;
#pragma unroll
        for (int mt = 0; mt < 2; mt++)
#pragma unroll
            for (int q = 0; q < 4; q++) {
                float c0 = run[mt][q][0], c1 = run[mt][q][1];
                float c2 = run[mt][q][2], c3 = run[mt][q][3];
                float ex0 = __shfl_xor_sync(0xffffffffu, c0, 1);
                float ex1 = __shfl_xor_sync(0xffffffffu, c1, 1);
                float ex2 = __shfl_xor_sync(0xffffffffu, c2, 1);
                float ex3 = __shfl_xor_sync(0xffffffffu, c3, 1);
                float gi, gf, gg, go;
                int row128 = wm * 32 + mt * 16 + (lane >> 2);
                if (!odd) { gi = c0;  gf = c1;  gg = ex0; go = ex1; }
                else      { gi = ex2; gf = ex3; gg = c2;  go = c3;  row128 += 8; }
                int U = nb * 16 + wn * 8 + q * 2 + ((lane & 3) >> 1);
                int rg = rb * 128 + row128;
                if (MODE == 0) {       // add precomputed fp32 tags contribution first
                    float4 pv = *(const float4*)&g_pre0[rg * 1024 + 4 * U];
                    gi += pv.x; gf += pv.y; gg += pv.z; go += pv.w;
                }
                const float* bi = &g_bias[layer][0][4 * U];
                const float* bh = &g_bias[layer][1][4 * U];
                float cold = g_cst[layer][rg * 256 + U];
                float cn = sigf((gf + bi[1]) + bh[1]) * cold
                         + sigf((gi + bi[0]) + bh[0]) * tanhf((gg + bi[2]) + bh[2]);
                g_cst[layer][rg * 256 + U] = cn;
                float h = sigf((go + bi[3]) + bh[3]) * tanhf(cn);
                __nv_bfloat16 s0, s1, s2;
                split3(h, s0, s1, s2);
                int off = row128 * 64 + (U & 63);
                int uc = U >> 6;
                g_hs[par ^ 1][layer][0][rb][uc][off] = s0;
                g_hs[par ^ 1][layer][1][rb][uc][off] = s1;
                g_hs[par ^ 1][layer][2][rb][uc][off] = s2;
            }
    }
}

// ---------------- argmax over ALL steps in one launch (first-max semantics) ----------------
__global__ void argmax_all(const float* __restrict__ d_probs, float* __restrict__ outs) {
    int warp = (blockIdx.x * blockDim.x + threadIdx.x) >> 5;
    int lane = threadIdx.x & 31;
    if (warp >= BSZ * NSTEP) return;
    int b = warp / NSTEP, s = warp - b * NSTEP;
    const float* row = d_probs + (b * 31 + s + 1) * 256;
    float best = -1e30f; int bi = 0;
#pragma unroll
    for (int j = 0; j < 8; j++) {
        int c = lane + j * 32;
        float v = row[c];
        if (v > best) { best = v; bi = c; }
    }
#pragma unroll
    for (int off = 16; off; off >>= 1) {
        float ov = __shfl_xor_sync(0xffffffffu, best, off);
        int   oi = __shfl_xor_sync(0xffffffffu, bi, off);
        if (ov > best || (ov == best && oi < bi)) { best = ov; bi = oi; }
    }
    if (lane == 0) outs[b * NSTEP + s] = (float)bi;
}

// ======================= launch =======================
extern "C" void kernel_launch(void* const* d_in, const int* in_sizes, int n_in,
                              void* d_out_v, int out_size)
{
    const float* tags = (const float*)d_in[2];
    const float* Wih0 = (const float*)d_in[13];
    const float* Whh0 = (const float*)d_in[14];
    const float* bih0 = (const float*)d_in[15];
    const float* bhh0 = (const float*)d_in[16];
    const float* Wih  = (const float*)d_in[17];
    const float* Whh  = (const float*)d_in[18];
    const float* bih  = (const float*)d_in[19];
    const float* bhh  = (const float*)d_in[20];
    const float* linW = (const float*)d_in[21];
    const float* linb = (const float*)d_in[22];
    float* d_out = (float*)d_out_v;

    cudaFuncSetAttribute(mma_kernel<0>, cudaFuncAttributeMaxDynamicSharedMemorySize, SMEM_TOTAL);
    cudaFuncSetAttribute(mma_kernel<1>, cudaFuncAttributeMaxDynamicSharedMemorySize, SMEM_TOTAL);
    cudaFuncSetAttribute(mma_kernel<2>, cudaFuncAttributeMaxDynamicSharedMemorySize, SMEM_TOTAL);

    bool has_outputs = (out_size >= PROBS_TOTAL + BSZ * NSTEP);

    {
        long total = 3L * BSZ * 256 + 3L * 3 * 32 * 4 * 8192 / 2
                   + (long)BSZ * 256 + 3 * 1024;
        k_setup<<<(unsigned)((total + 255) / 256), 256>>>(bih0, bhh0, bih, bhh, d_out);
    }
    {
        int nw = 1024 * 512 + 2 * 1024 * 512 + 256 * 256;
        k_build_w<<<(nw + 255) / 256, 256>>>(Wih0, Whh0, Wih, Whh, linW);
    }
    k_pre0<<<dim3(BSZ / 64, 1024 / 64), 256>>>(tags, Wih0);

    for (int s = 0; s < NSTEP; s++) {
        int par = s & 1;
        mma_kernel<0><<<dim3(32, 16), 256, SMEM_TOTAL>>>(0, par, s, nullptr, d_out);
        mma_kernel<1><<<dim3(32, 16), 256, SMEM_TOTAL>>>(1, par, s, nullptr, d_out);
        mma_kernel<1><<<dim3(32, 16), 256, SMEM_TOTAL>>>(2, par, s, nullptr, d_out);
        mma_kernel<2><<<dim3(32, 4), 256, SMEM_TOTAL>>>(0, par, s, linb, d_out);
    }
    if (has_outputs) {
        int nwarps = BSZ * NSTEP;
        argmax_all<<<(nwarps * 32 + 255) / 256, 256>>>(d_out, d_out + PROBS_TOTAL);
    }
}